// round 14
// baseline (speedup 1.0000x reference)
#include <cuda_runtime.h>
#include <cstdint>

#define DIN  32
#define DOUT 32
#define TPB  256
#define NWARP (TPB / 32)
#define RPT  2                              // rows per thread (X = 64 regs)
#define TILE_ROWS (32 * RPT)                // 64 rows per warp-tile
#define STRIDE_F  36                        // padded smem row stride (floats)
#define TILE_FLOATS (TILE_ROWS * STRIDE_F)  // 2304 floats = 9216 B per warp
#define SMEM_BYTES (NWARP * TILE_FLOATS * 4)  // 73728 B per block -> 2 blocks/SM

// W in constant memory: const port broadcasts uniform reads off the L1 crossbar
// (proven: dur 650 -> 345 us in round 10).
__constant__ __align__(16) float Wc[DOUT * DIN];

// Packed 2-wide fp32 FMA (Blackwell f32x2 pipe; PTX-only).
__device__ __forceinline__ unsigned long long fma2(unsigned long long a,
                                                   unsigned long long b,
                                                   unsigned long long c) {
    unsigned long long d;
    asm("fma.rn.f32x2 %0, %1, %2, %3;" : "=l"(d) : "l"(a), "l"(b), "l"(c));
    return d;
}

union U64F2 { unsigned long long u; float2 f; };

extern "C" __global__ void __launch_bounds__(TPB, 2)
layer_relu_kernel(const float* __restrict__ x,
                  float* __restrict__ out,
                  int nrows)
{
    extern __shared__ float smem[];
    const int lane = threadIdx.x & 31;
    const int wid  = threadIdx.x >> 5;
    float* tile = smem + wid * TILE_FLOATS;   // warp-private tile

    const int gwarp  = blockIdx.x * NWARP + wid;
    const int nwarps = gridDim.x * NWARP;     // persistent: ~55 tiles/warp
    const int ntiles = nrows / TILE_ROWS;

    for (int t = gwarp; t < ntiles; t += nwarps) {
        const long long rowBase = (long long)t * TILE_ROWS;

        // ---- Step 1: coalesced gmem -> smem (64 rows x 128 B), evict-first
        //      reads (lines are prefetched + read-once; free the L2 early).
        {
            const float4* gx = reinterpret_cast<const float4*>(x + rowBase * DIN);
            #pragma unroll
            for (int i = 0; i < 16; ++i) {
                const int idx = i * 32 + lane;            // float4 chunk 0..511
                float4 v = __ldcs(&gx[idx]);
                const int r = idx >> 3, c = idx & 7;
                *reinterpret_cast<float4*>(&tile[r * STRIDE_F + c * 4]) = v;
            }
        }

        // ---- Prefetch next tile's 16 KB into L2 (no regs / smem / sync).
        //      With the persistent grid this covers 54 of ~55 iterations.
        {
            const int nt = t + nwarps;
            if (nt < ntiles) {
                const char* nb = reinterpret_cast<const char*>(
                    x + (long long)nt * TILE_ROWS * DIN);
                #pragma unroll
                for (int i = 0; i < 4; ++i) {
                    const char* p = nb + (i * 32 + lane) * 128;
                    asm volatile("prefetch.global.L2 [%0];" :: "l"(p));
                }
            }
        }
        __syncwarp();

        // ---- Step 2: per-thread rows (lane, lane+32) -> registers
        unsigned long long X[RPT][16];
        #pragma unroll
        for (int rr = 0; rr < RPT; ++rr) {
            const int r = lane + 32 * rr;
            #pragma unroll
            for (int j = 0; j < 8; ++j) {
                ulonglong2 v = *reinterpret_cast<const ulonglong2*>(
                    &tile[r * STRIDE_F + j * 4]);
                X[rr][2 * j]     = v.x;
                X[rr][2 * j + 1] = v.y;
            }
        }
        __syncwarp();   // x-tile dead; results will overwrite it

        // ---- Step 3: compute. W from __constant__ (const port broadcast)
        #pragma unroll
        for (int og = 0; og < 8; ++og) {
            float res[RPT][4];
            #pragma unroll
            for (int c = 0; c < 4; ++c) {
                const int o = og * 4 + c;
                const ulonglong2* wr =
                    reinterpret_cast<const ulonglong2*>(&Wc[o * DIN]);
                #pragma unroll
                for (int rr = 0; rr < RPT; ++rr) {
                    unsigned long long acc = 0ull;
                    #pragma unroll
                    for (int j = 0; j < 8; ++j) {
                        const ulonglong2 w = wr[j];
                        acc = fma2(X[rr][2 * j],     w.x, acc);
                        acc = fma2(X[rr][2 * j + 1], w.y, acc);
                    }
                    U64F2 u; u.u = acc;
                    res[rr][c] = fmaxf(u.f.x + u.f.y, 0.0f);
                }
            }
            #pragma unroll
            for (int rr = 0; rr < RPT; ++rr) {
                const int r = lane + 32 * rr;
                *reinterpret_cast<float4*>(&tile[r * STRIDE_F + og * 4]) =
                    make_float4(res[rr][0], res[rr][1], res[rr][2], res[rr][3]);
            }
        }
        __syncwarp();

        // ---- Step 4: coalesced smem -> gmem, streaming stores (evict-first)
        {
            float4* gout = reinterpret_cast<float4*>(out + rowBase * DOUT);
            #pragma unroll
            for (int i = 0; i < 16; ++i) {
                const int idx = i * 32 + lane;
                const int r = idx >> 3, c = idx & 7;
                __stcs(&gout[idx], *reinterpret_cast<const float4*>(
                                       &tile[r * STRIDE_F + c * 4]));
            }
        }
        __syncwarp();
    }

    // ---- Tail: leftover rows (< TILE_ROWS); never taken for N=8388608
    const long long tailBase = (long long)ntiles * TILE_ROWS;
    if (tailBase < nrows && gwarp == 0) {
        for (long long r = tailBase + lane; r < nrows; r += 32) {
            float xv[DIN];
            #pragma unroll
            for (int k = 0; k < DIN; ++k) xv[k] = x[r * DIN + k];
            #pragma unroll
            for (int o = 0; o < DOUT; ++o) {
                float s = 0.f;
                #pragma unroll
                for (int k = 0; k < DIN; ++k)
                    s = fmaf(xv[k], Wc[o * DIN + k], s);
                out[r * DOUT + o] = fmaxf(s, 0.f);
            }
        }
    }
}

extern "C" void kernel_launch(void* const* d_in, const int* in_sizes, int n_in,
                              void* d_out, int out_size) {
    const float* x = (const float*)d_in[0];   // [N, 32] fp32
    const float* W = (const float*)d_in[1];   // [32, 32] fp32
    float* out     = (float*)d_out;           // [N, 32] fp32

    const int nrows = in_sizes[0] / DIN;      // 8388608

    cudaFuncSetAttribute(layer_relu_kernel,
                         cudaFuncAttributeMaxDynamicSharedMemorySize, SMEM_BYTES);

    // Device-to-device copy into the constant bank; captures as a memcpy node.
    cudaMemcpyToSymbolAsync(Wc, W, DOUT * DIN * sizeof(float), 0,
                            cudaMemcpyDeviceToDevice, 0);

    // Persistent grid: exactly 2 resident CTAs per SM -> zero CTA waves,
    // ~55 tiles per warp (prefetch covers all but the first).
    int nsm = 148;
    cudaDeviceGetAttribute(&nsm, cudaDevAttrMultiProcessorCount, 0);
    const int blocks = 2 * nsm;               // 304 on GB300
    layer_relu_kernel<<<blocks, TPB, SMEM_BYTES>>>(x, out, nrows);
}

// round 15
// speedup vs baseline: 1.1219x; 1.1219x over previous
#include <cuda_runtime.h>
#include <cstdint>

#define DIN  32
#define DOUT 32
#define TPB  256
#define NWARP (TPB / 32)
#define RPT  2                              // rows per thread (X = 64 regs)
#define TILE_ROWS (32 * RPT)                // 64 rows per warp-tile
#define STRIDE_F  36                        // padded smem row stride (floats)
#define TILE_FLOATS (TILE_ROWS * STRIDE_F)  // 2304 floats = 9216 B per warp
#define SMEM_BYTES (NWARP * TILE_FLOATS * 4)  // 73728 B per block -> 2 blocks/SM

// W in constant memory: const port broadcasts uniform reads off the L1 crossbar
// (proven: dur 650 -> 345 us in round 10).
__constant__ __align__(16) float Wc[DOUT * DIN];

// Packed 2-wide fp32 FMA (Blackwell f32x2 pipe; PTX-only).
__device__ __forceinline__ unsigned long long fma2(unsigned long long a,
                                                   unsigned long long b,
                                                   unsigned long long c) {
    unsigned long long d;
    asm("fma.rn.f32x2 %0, %1, %2, %3;" : "=l"(d) : "l"(a), "l"(b), "l"(c));
    return d;
}

union U64F2 { unsigned long long u; float2 f; };

extern "C" __global__ void __launch_bounds__(TPB, 2)
layer_relu_kernel(const float* __restrict__ x,
                  float* __restrict__ out,
                  int nrows)
{
    extern __shared__ float smem[];
    const int lane = threadIdx.x & 31;
    const int wid  = threadIdx.x >> 5;
    float* tile = smem + wid * TILE_FLOATS;   // warp-private tile

    const int gwarp  = blockIdx.x * NWARP + wid;
    const int nwarps = gridDim.x * NWARP;     // 8192 warps -> 16 tiles/warp
    const int ntiles = nrows / TILE_ROWS;

    for (int t = gwarp; t < ntiles; t += nwarps) {
        const long long rowBase = (long long)t * TILE_ROWS;

        // ---- Step 1: coalesced gmem -> smem (64 rows x 128 B)
        {
            const float4* gx = reinterpret_cast<const float4*>(x + rowBase * DIN);
            #pragma unroll
            for (int i = 0; i < 16; ++i) {
                const int idx = i * 32 + lane;            // float4 chunk 0..511
                float4 v = __ldg(&gx[idx]);
                const int r = idx >> 3, c = idx & 7;
                *reinterpret_cast<float4*>(&tile[r * STRIDE_F + c * 4]) = v;
            }
        }

        // ---- Prefetch next tile's 16 KB into L2 (no regs / smem / sync):
        //      converts next iteration's exposed DRAM latency into L2 latency.
        {
            const int nt = t + nwarps;
            if (nt < ntiles) {
                const char* nb = reinterpret_cast<const char*>(
                    x + (long long)nt * TILE_ROWS * DIN);
                #pragma unroll
                for (int i = 0; i < 4; ++i) {
                    const char* p = nb + (i * 32 + lane) * 128;
                    asm volatile("prefetch.global.L2 [%0];" :: "l"(p));
                }
            }
        }
        __syncwarp();

        // ---- Step 2: per-thread rows (lane, lane+32) -> registers
        unsigned long long X[RPT][16];
        #pragma unroll
        for (int rr = 0; rr < RPT; ++rr) {
            const int r = lane + 32 * rr;
            #pragma unroll
            for (int j = 0; j < 8; ++j) {
                ulonglong2 v = *reinterpret_cast<const ulonglong2*>(
                    &tile[r * STRIDE_F + j * 4]);
                X[rr][2 * j]     = v.x;
                X[rr][2 * j + 1] = v.y;
            }
        }
        __syncwarp();   // x-tile dead; results will overwrite it

        // ---- Step 3: compute. W from __constant__ (const port broadcast)
        #pragma unroll
        for (int og = 0; og < 8; ++og) {
            float res[RPT][4];
            #pragma unroll
            for (int c = 0; c < 4; ++c) {
                const int o = og * 4 + c;
                const ulonglong2* wr =
                    reinterpret_cast<const ulonglong2*>(&Wc[o * DIN]);
                #pragma unroll
                for (int rr = 0; rr < RPT; ++rr) {
                    unsigned long long acc = 0ull;
                    #pragma unroll
                    for (int j = 0; j < 8; ++j) {
                        const ulonglong2 w = wr[j];
                        acc = fma2(X[rr][2 * j],     w.x, acc);
                        acc = fma2(X[rr][2 * j + 1], w.y, acc);
                    }
                    U64F2 u; u.u = acc;
                    res[rr][c] = fmaxf(u.f.x + u.f.y, 0.0f);
                }
            }
            #pragma unroll
            for (int rr = 0; rr < RPT; ++rr) {
                const int r = lane + 32 * rr;
                *reinterpret_cast<float4*>(&tile[r * STRIDE_F + og * 4]) =
                    make_float4(res[rr][0], res[rr][1], res[rr][2], res[rr][3]);
            }
        }
        __syncwarp();

        // ---- Step 4: coalesced smem -> gmem, streaming stores (evict-first:
        //      out is write-once, keep L2 for the x-read stream)
        {
            float4* gout = reinterpret_cast<float4*>(out + rowBase * DOUT);
            #pragma unroll
            for (int i = 0; i < 16; ++i) {
                const int idx = i * 32 + lane;
                const int r = idx >> 3, c = idx & 7;
                __stcs(&gout[idx], *reinterpret_cast<const float4*>(
                                       &tile[r * STRIDE_F + c * 4]));
            }
        }
        __syncwarp();
    }

    // ---- Tail: leftover rows (< TILE_ROWS); never taken for N=8388608
    const long long tailBase = (long long)ntiles * TILE_ROWS;
    if (tailBase < nrows && gwarp == 0) {
        for (long long r = tailBase + lane; r < nrows; r += 32) {
            float xv[DIN];
            #pragma unroll
            for (int k = 0; k < DIN; ++k) xv[k] = x[r * DIN + k];
            #pragma unroll
            for (int o = 0; o < DOUT; ++o) {
                float s = 0.f;
                #pragma unroll
                for (int k = 0; k < DIN; ++k)
                    s = fmaf(xv[k], Wc[o * DIN + k], s);
                out[r * DOUT + o] = fmaxf(s, 0.f);
            }
        }
    }
}

extern "C" void kernel_launch(void* const* d_in, const int* in_sizes, int n_in,
                              void* d_out, int out_size) {
    const float* x = (const float*)d_in[0];   // [N, 32] fp32
    const float* W = (const float*)d_in[1];   // [32, 32] fp32
    float* out     = (float*)d_out;           // [N, 32] fp32

    const int nrows = in_sizes[0] / DIN;      // 8388608

    cudaFuncSetAttribute(layer_relu_kernel,
                         cudaFuncAttributeMaxDynamicSharedMemorySize, SMEM_BYTES);

    // Device-to-device copy into the constant bank; captures as a memcpy node.
    cudaMemcpyToSymbolAsync(Wc, W, DOUT * DIN * sizeof(float), 0,
                            cudaMemcpyDeviceToDevice, 0);

    // ~3.4 waves: keeps wave-level work-steal rebalancing (persistent grid's
    // single wave regressed: no rebalance -> idle tail), while cutting cold
    // first-iterations 25% -> 12.5% and wave transitions 13 -> 3 vs grid=4096.
    const int blocks = 1024;                  // 16 tiles per warp
    layer_relu_kernel<<<blocks, TPB, SMEM_BYTES>>>(x, out, nrows);
}

// round 16
// speedup vs baseline: 1.2156x; 1.0834x over previous
#include <cuda_runtime.h>
#include <cstdint>

#define DIN  32
#define DOUT 32
#define TPB  256
#define NWARP (TPB / 32)
#define RPT  2                              // rows per thread (X = 64 regs)
#define TILE_ROWS (32 * RPT)                // 64 rows per warp-tile
#define STRIDE_F  36                        // padded smem row stride (floats)
#define TILE_FLOATS (TILE_ROWS * STRIDE_F)  // 2304 floats = 9216 B per warp
#define SMEM_BYTES (NWARP * TILE_FLOATS * 4)  // 73728 B per block -> 2 blocks/SM

// W in constant memory: const port broadcasts uniform reads off the L1 crossbar
// (proven: dur 650 -> 345 us in round 10).
__constant__ __align__(16) float Wc[DOUT * DIN];

// Packed 2-wide fp32 FMA (Blackwell f32x2 pipe; PTX-only).
__device__ __forceinline__ unsigned long long fma2(unsigned long long a,
                                                   unsigned long long b,
                                                   unsigned long long c) {
    unsigned long long d;
    asm("fma.rn.f32x2 %0, %1, %2, %3;" : "=l"(d) : "l"(a), "l"(b), "l"(c));
    return d;
}

union U64F2 { unsigned long long u; float2 f; };

extern "C" __global__ void __launch_bounds__(TPB, 2)
layer_relu_kernel(const float* __restrict__ x,
                  float* __restrict__ out,
                  int nrows)
{
    extern __shared__ float smem[];
    const int lane = threadIdx.x & 31;
    const int wid  = threadIdx.x >> 5;
    float* tile = smem + wid * TILE_FLOATS;   // warp-private tile

    const int gwarp  = blockIdx.x * NWARP + wid;
    const int nwarps = gridDim.x * NWARP;     // 65536 warps -> 2 tiles/warp
    const int ntiles = nrows / TILE_ROWS;

    for (int t = gwarp; t < ntiles; t += nwarps) {
        const long long rowBase = (long long)t * TILE_ROWS;

        // ---- Step 1: coalesced gmem -> smem (64 rows x 128 B)
        {
            const float4* gx = reinterpret_cast<const float4*>(x + rowBase * DIN);
            #pragma unroll
            for (int i = 0; i < 16; ++i) {
                const int idx = i * 32 + lane;            // float4 chunk 0..511
                float4 v = __ldg(&gx[idx]);
                const int r = idx >> 3, c = idx & 7;
                *reinterpret_cast<float4*>(&tile[r * STRIDE_F + c * 4]) = v;
            }
        }

        // ---- Prefetch next tile's 16 KB into L2 (no regs / smem / sync):
        //      converts next iteration's exposed DRAM latency into L2 latency.
        {
            const int nt = t + nwarps;
            if (nt < ntiles) {
                const char* nb = reinterpret_cast<const char*>(
                    x + (long long)nt * TILE_ROWS * DIN);
                #pragma unroll
                for (int i = 0; i < 4; ++i) {
                    const char* p = nb + (i * 32 + lane) * 128;
                    asm volatile("prefetch.global.L2 [%0];" :: "l"(p));
                }
            }
        }
        __syncwarp();

        // ---- Step 2: per-thread rows (lane, lane+32) -> registers
        unsigned long long X[RPT][16];
        #pragma unroll
        for (int rr = 0; rr < RPT; ++rr) {
            const int r = lane + 32 * rr;
            #pragma unroll
            for (int j = 0; j < 8; ++j) {
                ulonglong2 v = *reinterpret_cast<const ulonglong2*>(
                    &tile[r * STRIDE_F + j * 4]);
                X[rr][2 * j]     = v.x;
                X[rr][2 * j + 1] = v.y;
            }
        }
        __syncwarp();   // x-tile dead; results will overwrite it

        // ---- Step 3: compute. W from __constant__ (const port broadcast)
        #pragma unroll
        for (int og = 0; og < 8; ++og) {
            float res[RPT][4];
            #pragma unroll
            for (int c = 0; c < 4; ++c) {
                const int o = og * 4 + c;
                const ulonglong2* wr =
                    reinterpret_cast<const ulonglong2*>(&Wc[o * DIN]);
                #pragma unroll
                for (int rr = 0; rr < RPT; ++rr) {
                    unsigned long long acc = 0ull;
                    #pragma unroll
                    for (int j = 0; j < 8; ++j) {
                        const ulonglong2 w = wr[j];
                        acc = fma2(X[rr][2 * j],     w.x, acc);
                        acc = fma2(X[rr][2 * j + 1], w.y, acc);
                    }
                    U64F2 u; u.u = acc;
                    res[rr][c] = fmaxf(u.f.x + u.f.y, 0.0f);
                }
            }
            #pragma unroll
            for (int rr = 0; rr < RPT; ++rr) {
                const int r = lane + 32 * rr;
                *reinterpret_cast<float4*>(&tile[r * STRIDE_F + og * 4]) =
                    make_float4(res[rr][0], res[rr][1], res[rr][2], res[rr][3]);
            }
        }
        __syncwarp();

        // ---- Step 4: coalesced smem -> gmem, streaming stores (evict-first:
        //      out is write-once, keep L2 for the x-read stream)
        {
            float4* gout = reinterpret_cast<float4*>(out + rowBase * DOUT);
            #pragma unroll
            for (int i = 0; i < 16; ++i) {
                const int idx = i * 32 + lane;
                const int r = idx >> 3, c = idx & 7;
                __stcs(&gout[idx], *reinterpret_cast<const float4*>(
                                       &tile[r * STRIDE_F + c * 4]));
            }
        }
        __syncwarp();
    }

    // ---- Tail: leftover rows (< TILE_ROWS); never taken for N=8388608
    const long long tailBase = (long long)ntiles * TILE_ROWS;
    if (tailBase < nrows && gwarp == 0) {
        for (long long r = tailBase + lane; r < nrows; r += 32) {
            float xv[DIN];
            #pragma unroll
            for (int k = 0; k < DIN; ++k) xv[k] = x[r * DIN + k];
            #pragma unroll
            for (int o = 0; o < DOUT; ++o) {
                float s = 0.f;
                #pragma unroll
                for (int k = 0; k < DIN; ++k)
                    s = fmaf(xv[k], Wc[o * DIN + k], s);
                out[r * DOUT + o] = fmaxf(s, 0.f);
            }
        }
    }
}

extern "C" void kernel_launch(void* const* d_in, const int* in_sizes, int n_in,
                              void* d_out, int out_size) {
    const float* x = (const float*)d_in[0];   // [N, 32] fp32
    const float* W = (const float*)d_in[1];   // [32, 32] fp32
    float* out     = (float*)d_out;           // [N, 32] fp32

    const int nrows = in_sizes[0] / DIN;      // 8388608

    cudaFuncSetAttribute(layer_relu_kernel,
                         cudaFuncAttributeMaxDynamicSharedMemorySize, SMEM_BYTES);

    // Device-to-device copy into the constant bank; captures as a memcpy node.
    cudaMemcpyToSymbolAsync(Wc, W, DOUT * DIN * sizeof(float), 0,
                            cudaMemcpyDeviceToDevice, 0);

    // Grid sweep measured: 304 -> 425us, 1024 -> 379us, 4096 -> 340us
    // (monotone: finer CTA granularity = better rebalance + shorter drain).
    // Continue the trend: 8192 CTAs, 2 tiles/warp.
    const int blocks = 8192;
    layer_relu_kernel<<<blocks, TPB, SMEM_BYTES>>>(x, out, nrows);
}

// round 17
// speedup vs baseline: 1.2519x; 1.0299x over previous
#include <cuda_runtime.h>
#include <cstdint>

#define DIN  32
#define DOUT 32
#define TPB  256
#define NWARP (TPB / 32)
#define RPT  2                              // rows per thread (X = 64 regs)
#define TILE_ROWS (32 * RPT)                // 64 rows per warp-tile
#define STRIDE_F  36                        // padded smem row stride (floats)
#define TILE_FLOATS (TILE_ROWS * STRIDE_F)  // 2304 floats = 9216 B per warp
#define SMEM_BYTES (NWARP * TILE_FLOATS * 4)  // 73728 B per block -> 2 blocks/SM

// W in constant memory: the constant port broadcasts uniform reads to all 32
// lanes for free, entirely off the L1/smem return crossbar (which charges full
// 512B width for ANY replicated delivery — smem broadcast and uniform LDG
// alike; proven across rounds 1/5/9/10: 901 -> 650 -> 345 us).
__constant__ __align__(16) float Wc[DOUT * DIN];

// Packed 2-wide fp32 FMA (Blackwell f32x2 pipe; PTX-only, ptxas never fuses).
__device__ __forceinline__ unsigned long long fma2(unsigned long long a,
                                                   unsigned long long b,
                                                   unsigned long long c) {
    unsigned long long d;
    asm("fma.rn.f32x2 %0, %1, %2, %3;" : "=l"(d) : "l"(a), "l"(b), "l"(c));
    return d;
}

union U64F2 { unsigned long long u; float2 f; };

extern "C" __global__ void __launch_bounds__(TPB, 2)
layer_relu_kernel(const float* __restrict__ x,
                  float* __restrict__ out,
                  int nrows)
{
    extern __shared__ float smem[];
    const int lane = threadIdx.x & 31;
    const int wid  = threadIdx.x >> 5;
    float* tile = smem + wid * TILE_FLOATS;   // warp-private tile

    const int gwarp  = blockIdx.x * NWARP + wid;
    const int nwarps = gridDim.x * NWARP;     // 32768 warps -> 4 tiles/warp
    const int ntiles = nrows / TILE_ROWS;

    for (int t = gwarp; t < ntiles; t += nwarps) {
        const long long rowBase = (long long)t * TILE_ROWS;

        // ---- Step 1: coalesced gmem -> smem (64 rows x 128 B)
        {
            const float4* gx = reinterpret_cast<const float4*>(x + rowBase * DIN);
            #pragma unroll
            for (int i = 0; i < 16; ++i) {
                const int idx = i * 32 + lane;            // float4 chunk 0..511
                float4 v = __ldg(&gx[idx]);
                const int r = idx >> 3, c = idx & 7;
                *reinterpret_cast<float4*>(&tile[r * STRIDE_F + c * 4]) = v;
            }
        }

        // ---- Prefetch next tile's 16 KB into L2 (no regs / smem / sync):
        //      converts next iteration's exposed DRAM latency into L2 latency.
        {
            const int nt = t + nwarps;
            if (nt < ntiles) {
                const char* nb = reinterpret_cast<const char*>(
                    x + (long long)nt * TILE_ROWS * DIN);
                #pragma unroll
                for (int i = 0; i < 4; ++i) {
                    const char* p = nb + (i * 32 + lane) * 128;
                    asm volatile("prefetch.global.L2 [%0];" :: "l"(p));
                }
            }
        }
        __syncwarp();

        // ---- Step 2: per-thread rows (lane, lane+32) -> registers
        unsigned long long X[RPT][16];
        #pragma unroll
        for (int rr = 0; rr < RPT; ++rr) {
            const int r = lane + 32 * rr;
            #pragma unroll
            for (int j = 0; j < 8; ++j) {
                ulonglong2 v = *reinterpret_cast<const ulonglong2*>(
                    &tile[r * STRIDE_F + j * 4]);
                X[rr][2 * j]     = v.x;
                X[rr][2 * j + 1] = v.y;
            }
        }
        __syncwarp();   // x-tile dead; results will overwrite it

        // ---- Step 3: compute. W from __constant__ (const port broadcast)
        #pragma unroll
        for (int og = 0; og < 8; ++og) {
            float res[RPT][4];
            #pragma unroll
            for (int c = 0; c < 4; ++c) {
                const int o = og * 4 + c;
                const ulonglong2* wr =
                    reinterpret_cast<const ulonglong2*>(&Wc[o * DIN]);
                #pragma unroll
                for (int rr = 0; rr < RPT; ++rr) {
                    unsigned long long acc = 0ull;
                    #pragma unroll
                    for (int j = 0; j < 8; ++j) {
                        const ulonglong2 w = wr[j];
                        acc = fma2(X[rr][2 * j],     w.x, acc);
                        acc = fma2(X[rr][2 * j + 1], w.y, acc);
                    }
                    U64F2 u; u.u = acc;
                    res[rr][c] = fmaxf(u.f.x + u.f.y, 0.0f);
                }
            }
            #pragma unroll
            for (int rr = 0; rr < RPT; ++rr) {
                const int r = lane + 32 * rr;
                *reinterpret_cast<float4*>(&tile[r * STRIDE_F + og * 4]) =
                    make_float4(res[rr][0], res[rr][1], res[rr][2], res[rr][3]);
            }
        }
        __syncwarp();

        // ---- Step 4: coalesced smem -> gmem, streaming stores (evict-first:
        //      out is write-once, keep L2 for the x-read stream)
        {
            float4* gout = reinterpret_cast<float4*>(out + rowBase * DOUT);
            #pragma unroll
            for (int i = 0; i < 16; ++i) {
                const int idx = i * 32 + lane;
                const int r = idx >> 3, c = idx & 7;
                __stcs(&gout[idx], *reinterpret_cast<const float4*>(
                                       &tile[r * STRIDE_F + c * 4]));
            }
        }
        __syncwarp();
    }

    // ---- Tail: leftover rows (< TILE_ROWS); never taken for N=8388608
    const long long tailBase = (long long)ntiles * TILE_ROWS;
    if (tailBase < nrows && gwarp == 0) {
        for (long long r = tailBase + lane; r < nrows; r += 32) {
            float xv[DIN];
            #pragma unroll
            for (int k = 0; k < DIN; ++k) xv[k] = x[r * DIN + k];
            #pragma unroll
            for (int o = 0; o < DOUT; ++o) {
                float s = 0.f;
                #pragma unroll
                for (int k = 0; k < DIN; ++k)
                    s = fmaf(xv[k], Wc[o * DIN + k], s);
                out[r * DOUT + o] = fmaxf(s, 0.f);
            }
        }
    }
}

extern "C" void kernel_launch(void* const* d_in, const int* in_sizes, int n_in,
                              void* d_out, int out_size) {
    const float* x = (const float*)d_in[0];   // [N, 32] fp32
    const float* W = (const float*)d_in[1];   // [32, 32] fp32
    float* out     = (float*)d_out;           // [N, 32] fp32

    const int nrows = in_sizes[0] / DIN;      // 8388608

    cudaFuncSetAttribute(layer_relu_kernel,
                         cudaFuncAttributeMaxDynamicSharedMemorySize, SMEM_BYTES);

    // Device-to-device copy into the constant bank; captures as a memcpy node.
    cudaMemcpyToSymbolAsync(Wc, W, DOUT * DIN * sizeof(float), 0,
                            cudaMemcpyDeviceToDevice, 0);

    // Grid sweep measured: 304 -> 425us, 1024 -> 379us, 4096 -> 340us,
    // 8192 -> 350us. 4096 (4 tiles/warp, ~13 waves) is the parabola minimum:
    // enough waves for work-steal rebalancing, short enough drain tail.
    const int blocks = 4096;
    layer_relu_kernel<<<blocks, TPB, SMEM_BYTES>>>(x, out, nrows);
}